// round 14
// baseline (speedup 1.0000x reference)
#include <cuda_runtime.h>
#include <cuda_bf16.h>
#include <math.h>

// Problem constants
#define B_   4
#define N_   512
#define FIN  64
#define FOUT 128
#define NCH  8           // i-chunks (64 i per chunk) — matches K2 grid.y

// Scratch (allocation-free rule: __device__ globals)
static __device__ float g_pi   [B_ * N_ * FOUT];          // nodes @ edge_W[:,F:].T
static __device__ float g_pjb  [B_ * N_ * FOUT];          // nodes @ edge_W[:,:F].T + edge_b
static __device__ float g_h    [B_ * N_ * FOUT];          // full MLP output
static __device__ float g_part [B_ * NCH * N_ * FOUT];    // partial sum_i edges (8MB)

__device__ __forceinline__ float celu1(float x) {
    return x > 0.f ? x : expm1f(x);
}

// ---------------------------------------------------------------------------
// K1a: edge projections only (proven R8 eW phase, separately compiled).
// grid = B*N/8 = 256 blocks, 128 threads.
// ---------------------------------------------------------------------------
__global__ __launch_bounds__(128) void k1a_ew(
    const float* __restrict__ nodes,
    const float* __restrict__ eW, const float* __restrict__ eb)
{
    const int row0 = blockIdx.x * 8;
    const int f    = threadIdx.x;

    __shared__ float xs[8 * FIN];
    {
        const float4* gx = (const float4*)(nodes + (size_t)row0 * FIN);
        ((float4*)xs)[f] = gx[f];
    }
    __syncthreads();
    const float4* x4 = (const float4*)xs;

    const float4* wr = (const float4*)(eW + (size_t)f * (2 * FIN));
    float accj[8], acci[8];
    #pragma unroll
    for (int r = 0; r < 8; r++) { accj[r] = 0.f; acci[r] = 0.f; }
    #pragma unroll
    for (int k = 0; k < 16; k++) {
        float4 wj = wr[k];
        float4 wi = wr[k + 16];
        #pragma unroll
        for (int r = 0; r < 8; r++) {
            float4 xv = x4[r * 16 + k];
            accj[r] += wj.x*xv.x + wj.y*xv.y + wj.z*xv.z + wj.w*xv.w;
            acci[r] += wi.x*xv.x + wi.y*xv.y + wi.z*xv.z + wi.w*xv.w;
        }
    }
    const float ebf = eb[f];
    #pragma unroll
    for (int r = 0; r < 8; r++) {
        g_pjb[(size_t)(row0 + r) * FOUT + f] = accj[r] + ebf;
        g_pi [(size_t)(row0 + r) * FOUT + f] = acci[r];
    }
}

// ---------------------------------------------------------------------------
// K1b: 3-layer CELU MLP (proven R8 MLP phase). Runs on a side stream,
// concurrent with K1a+K2 (g_h is consumed only by K3 after the join).
// grid = B*N/8 = 256 blocks, 128 threads.
// ---------------------------------------------------------------------------
__global__ __launch_bounds__(128) void k1b_mlp(
    const float* __restrict__ nodes,
    const float* __restrict__ W0, const float* __restrict__ b0,
    const float* __restrict__ W1, const float* __restrict__ b1,
    const float* __restrict__ W2, const float* __restrict__ b2)
{
    const int row0 = blockIdx.x * 8;
    const int f    = threadIdx.x;

    __shared__ float xs [8 * FIN];
    __shared__ float h0s[8 * FOUT];
    __shared__ float h1s[8 * FOUT];

    {
        const float4* gx = (const float4*)(nodes + (size_t)row0 * FIN);
        ((float4*)xs)[f] = gx[f];
    }
    __syncthreads();

    const float4* x4  = (const float4*)xs;
    const float4* h04 = (const float4*)h0s;
    const float4* h14 = (const float4*)h1s;

    // layer 0 (K=64) + CELU
    {
        const float4* wr = (const float4*)(W0 + (size_t)f * FIN);
        const float   bf = b0[f];
        float a[8];
        #pragma unroll
        for (int r = 0; r < 8; r++) a[r] = bf;
        #pragma unroll
        for (int k = 0; k < 16; k++) {
            float4 w = wr[k];
            #pragma unroll
            for (int r = 0; r < 8; r++) {
                float4 xv = x4[r * 16 + k];
                a[r] += w.x*xv.x + w.y*xv.y + w.z*xv.z + w.w*xv.w;
            }
        }
        #pragma unroll
        for (int r = 0; r < 8; r++) h0s[r * FOUT + f] = celu1(a[r]);
    }
    __syncthreads();

    // layer 1 (K=128) + CELU
    {
        const float4* wr = (const float4*)(W1 + (size_t)f * FOUT);
        const float   bf = b1[f];
        float a[8];
        #pragma unroll
        for (int r = 0; r < 8; r++) a[r] = bf;
        #pragma unroll
        for (int k = 0; k < 32; k++) {
            float4 w = wr[k];
            #pragma unroll
            for (int r = 0; r < 8; r++) {
                float4 hv = h04[r * 32 + k];
                a[r] += w.x*hv.x + w.y*hv.y + w.z*hv.z + w.w*hv.w;
            }
        }
        #pragma unroll
        for (int r = 0; r < 8; r++) h1s[r * FOUT + f] = celu1(a[r]);
    }
    __syncthreads();

    // layer 2 (K=128) -> g_h
    {
        const float4* wr = (const float4*)(W2 + (size_t)f * FOUT);
        const float   bf = b2[f];
        float a[8];
        #pragma unroll
        for (int r = 0; r < 8; r++) a[r] = bf;
        #pragma unroll
        for (int k = 0; k < 32; k++) {
            float4 w = wr[k];
            #pragma unroll
            for (int r = 0; r < 8; r++) {
                float4 hv = h14[r * 32 + k];
                a[r] += w.x*hv.x + w.y*hv.y + w.z*hv.z + w.w*hv.w;
            }
        }
        #pragma unroll
        for (int r = 0; r < 8; r++)
            g_h[(size_t)(row0 + r) * FOUT + f] = a[r];
    }
}

// ---------------------------------------------------------------------------
// K2: edges writer WITH fused i-partial reduction. (unchanged — proven)
// Tile: 64 (i) x 16 (j) per block. grid = (N/16, N/64, B) = 32x8x4, 256 thr.
// ---------------------------------------------------------------------------
__global__ __launch_bounds__(256) void k2_edges(
    const float* __restrict__ sk, float* __restrict__ edges)
{
    const int b  = blockIdx.z;
    const int iy = blockIdx.y;           // i-chunk 0..7
    const int i0 = iy * 64;
    const int j0 = blockIdx.x * 16;
    const int tid = threadIdx.x;

    __shared__ float4 spi [64][32];      // 32KB
    __shared__ float4 spjb[16][32];      // 8KB
    __shared__ float  ssk [64][16];      // 4KB

    const float4* gpi  = (const float4*)(g_pi  + ((size_t)(b * N_ + i0)) * FOUT);
    const float4* gpjb = (const float4*)(g_pjb + ((size_t)(b * N_ + j0)) * FOUT);
    #pragma unroll
    for (int t = tid; t < 2048; t += 256)
        spi[t >> 5][t & 31] = gpi[t];
    #pragma unroll
    for (int t = tid; t < 512; t += 256)
        spjb[t >> 5][t & 31] = gpjb[t];
    #pragma unroll
    for (int t = tid; t < 1024; t += 256) {
        int ii = t >> 4, jj = t & 15;
        ssk[ii][jj] = sk[((size_t)(b * N_ + i0 + ii)) * N_ + j0 + jj];
    }
    __syncthreads();

    const int lane = tid & 31;
    const int w    = tid >> 5;           // warp 0..7 -> jj in {w, w+8}

    const float4 c0 = spjb[w][lane];
    const float4 c1 = spjb[w + 8][lane];

    float4 acc0 = make_float4(0.f, 0.f, 0.f, 0.f);
    float4 acc1 = make_float4(0.f, 0.f, 0.f, 0.f);

    float4* __restrict__ e4 = (float4*)edges;
    const size_t base = ((size_t)(b * N_ + i0) * N_ + j0) * 32 + lane;

    #pragma unroll 4
    for (int ii = 0; ii < 64; ii++) {
        float4 a  = spi[ii][lane];
        float  s0 = ssk[ii][w];
        float  s1 = ssk[ii][w + 8];
        float4 e0, e1;
        e0.x = (a.x + c0.x) * s0;  e0.y = (a.y + c0.y) * s0;
        e0.z = (a.z + c0.z) * s0;  e0.w = (a.w + c0.w) * s0;
        e1.x = (a.x + c1.x) * s1;  e1.y = (a.y + c1.y) * s1;
        e1.z = (a.z + c1.z) * s1;  e1.w = (a.w + c1.w) * s1;
        size_t rbase = base + (size_t)ii * (N_ * 32);
        __stcs(&e4[rbase + (size_t)w * 32],        e0);
        __stcs(&e4[rbase + (size_t)(w + 8) * 32],  e1);
        acc0.x += e0.x; acc0.y += e0.y; acc0.z += e0.z; acc0.w += e0.w;
        acc1.x += e1.x; acc1.y += e1.y; acc1.z += e1.z; acc1.w += e1.w;
    }

    // write partials: g_part[b][iy][j][f]  (FULL edge sums — nothing added later)
    float4* p4 = (float4*)g_part;
    size_t pbase = (((size_t)(b * NCH + iy) * N_) + j0) * 32 + lane;
    p4[pbase + (size_t)w * 32]       = acc0;
    p4[pbase + (size_t)(w + 8) * 32] = acc1;
}

// ---------------------------------------------------------------------------
// K3: vectorized fold + 4-row node_W GEMV + h add.
// grid = (N/4, B) = 512 blocks, 128 threads.
//   fold: thread t owns float4 slot (jj = t>>5, v = t&31); folds 8 LDG.128.
//   GEMV: thread f computes 4 output rows (16 FMA per nW LDG.128).
// ---------------------------------------------------------------------------
__global__ __launch_bounds__(128) void k3_final(
    const float* __restrict__ nW, const float* __restrict__ nb,
    float* __restrict__ out1)
{
    const int b  = blockIdx.y;
    const int j0 = blockIdx.x * 4;
    const int f  = threadIdx.x;

    __shared__ float nn[4 * FOUT];       // 4 rows x 128

    // --- fold partials (float4, 8-way MLP) ---
    {
        const int jj = f >> 5;           // 0..3
        const int v  = f & 31;           // 0..31 (float4 index)
        const float4* p4 = (const float4*)g_part;
        const size_t rowslot = ((size_t)b * NCH * N_ + (j0 + jj)) * 32 + v;
        float4 a = make_float4(0.f, 0.f, 0.f, 0.f);
        #pragma unroll
        for (int c = 0; c < NCH; c++) {
            float4 p = p4[rowslot + (size_t)c * (N_ * 32)];
            a.x += p.x; a.y += p.y; a.z += p.z; a.w += p.w;
        }
        ((float4*)nn)[jj * 32 + v] = a;
    }
    __syncthreads();

    // --- node_W GEMV for 4 rows ---
    const float nbf = nb[f];
    float o0 = nbf, o1 = nbf, o2 = nbf, o3 = nbf;
    const float4* nwr = (const float4*)(nW + (size_t)f * FOUT);
    const float4* nn4 = (const float4*)nn;
    #pragma unroll 8
    for (int k = 0; k < 32; k++) {
        float4 w  = nwr[k];
        float4 n0 = nn4[k];
        float4 n1 = nn4[32 + k];
        float4 n2 = nn4[64 + k];
        float4 n3 = nn4[96 + k];
        o0 += w.x*n0.x + w.y*n0.y + w.z*n0.z + w.w*n0.w;
        o1 += w.x*n1.x + w.y*n1.y + w.z*n1.z + w.w*n1.w;
        o2 += w.x*n2.x + w.y*n2.y + w.z*n2.z + w.w*n2.w;
        o3 += w.x*n3.x + w.y*n3.y + w.z*n3.z + w.w*n3.w;
    }

    const float* hr = g_h + ((size_t)(b * N_ + j0)) * FOUT;
    out1[((size_t)(b * N_ + j0))     * FOUT + f] = o0 + hr[f];
    out1[((size_t)(b * N_ + j0 + 1)) * FOUT + f] = o1 + hr[FOUT + f];
    out1[((size_t)(b * N_ + j0 + 2)) * FOUT + f] = o2 + hr[2 * FOUT + f];
    out1[((size_t)(b * N_ + j0 + 3)) * FOUT + f] = o3 + hr[3 * FOUT + f];
}

// ---------------------------------------------------------------------------
extern "C" void kernel_launch(void* const* d_in, const int* in_sizes, int n_in,
                              void* d_out, int out_size)
{
    const float* nodes = (const float*)d_in[0];
    const float* sk    = (const float*)d_in[1];
    const float* eW    = (const float*)d_in[2];
    const float* eb    = (const float*)d_in[3];
    const float* nW    = (const float*)d_in[4];
    const float* nb    = (const float*)d_in[5];
    const float* W0    = (const float*)d_in[6];
    const float* b0    = (const float*)d_in[7];
    const float* W1    = (const float*)d_in[8];
    const float* b1    = (const float*)d_in[9];
    const float* W2    = (const float*)d_in[10];
    const float* b2    = (const float*)d_in[11];

    float* out1  = (float*)d_out;                            // [B,N,F_OUT]
    float* edges = (float*)d_out + (size_t)B_ * N_ * FOUT;   // [B,N,N,F_OUT]

    // Side stream + events, created once (lazily, outside graph capture).
    static cudaStream_t s2 = nullptr;
    static cudaEvent_t  evFork = nullptr, evJoin = nullptr;
    if (s2 == nullptr) {
        cudaStreamCreateWithFlags(&s2, cudaStreamNonBlocking);
        cudaEventCreateWithFlags(&evFork, cudaEventDisableTiming);
        cudaEventCreateWithFlags(&evJoin, cudaEventDisableTiming);
    }

    // Fork: MLP runs concurrently with projections + edges writer.
    cudaEventRecord(evFork, 0);
    cudaStreamWaitEvent(s2, evFork, 0);
    k1b_mlp<<<(B_ * N_) / 8, 128, 0, s2>>>(nodes, W0, b0, W1, b1, W2, b2);
    cudaEventRecord(evJoin, s2);

    // Main stream: projections -> edges (+fused partial reduction)
    k1a_ew<<<(B_ * N_) / 8, 128>>>(nodes, eW, eb);

    dim3 g2(N_ / 16, N_ / 64, B_);
    k2_edges<<<g2, 256>>>(sk, edges);

    // Join: K3 needs both g_part (main stream) and g_h (side stream).
    cudaStreamWaitEvent(0, evJoin, 0);
    dim3 g3(N_ / 4, B_);
    k3_final<<<g3, 128>>>(nW, nb, out1);
}

// round 15
// speedup vs baseline: 1.4248x; 1.4248x over previous
#include <cuda_runtime.h>
#include <cuda_bf16.h>
#include <math.h>

// Problem constants
#define B_   4
#define N_   512
#define FIN  64
#define FOUT 128
#define NCH  8           // i-chunks (64 i per chunk) — matches K2 grid.y

// Scratch (allocation-free rule: __device__ globals)
static __device__ float g_pi   [B_ * N_ * FOUT];          // nodes @ edge_W[:,F:].T
static __device__ float g_pjb  [B_ * N_ * FOUT];          // nodes @ edge_W[:,:F].T + edge_b
static __device__ float g_h    [B_ * N_ * FOUT];          // full MLP output
static __device__ float g_part [B_ * NCH * N_ * FOUT];    // partial sum_i edges (8MB)

__device__ __forceinline__ float celu1(float x) {
    return x > 0.f ? x : expm1f(x);
}

// ---------------------------------------------------------------------------
// K1a: edge projections only (proven R8/R13 eW phase).
// grid = B*N/8 = 256 blocks, 128 threads.
// ---------------------------------------------------------------------------
__global__ __launch_bounds__(128) void k1a_ew(
    const float* __restrict__ nodes,
    const float* __restrict__ eW, const float* __restrict__ eb)
{
    const int row0 = blockIdx.x * 8;
    const int f    = threadIdx.x;

    __shared__ float xs[8 * FIN];
    {
        const float4* gx = (const float4*)(nodes + (size_t)row0 * FIN);
        ((float4*)xs)[f] = gx[f];
    }
    __syncthreads();
    const float4* x4 = (const float4*)xs;

    const float4* wr = (const float4*)(eW + (size_t)f * (2 * FIN));
    float accj[8], acci[8];
    #pragma unroll
    for (int r = 0; r < 8; r++) { accj[r] = 0.f; acci[r] = 0.f; }
    #pragma unroll
    for (int k = 0; k < 16; k++) {
        float4 wj = wr[k];
        float4 wi = wr[k + 16];
        #pragma unroll
        for (int r = 0; r < 8; r++) {
            float4 xv = x4[r * 16 + k];
            accj[r] += wj.x*xv.x + wj.y*xv.y + wj.z*xv.z + wj.w*xv.w;
            acci[r] += wi.x*xv.x + wi.y*xv.y + wi.z*xv.z + wi.w*xv.w;
        }
    }
    const float ebf = eb[f];
    #pragma unroll
    for (int r = 0; r < 8; r++) {
        g_pjb[(size_t)(row0 + r) * FOUT + f] = accj[r] + ebf;
        g_pi [(size_t)(row0 + r) * FOUT + f] = acci[r];
    }
}

// ---------------------------------------------------------------------------
// K1b: 3-layer CELU MLP (proven). Side stream, concurrent with K1a+K2.
// grid = B*N/8 = 256 blocks, 128 threads.
// ---------------------------------------------------------------------------
__global__ __launch_bounds__(128) void k1b_mlp(
    const float* __restrict__ nodes,
    const float* __restrict__ W0, const float* __restrict__ b0,
    const float* __restrict__ W1, const float* __restrict__ b1,
    const float* __restrict__ W2, const float* __restrict__ b2)
{
    const int row0 = blockIdx.x * 8;
    const int f    = threadIdx.x;

    __shared__ float xs [8 * FIN];
    __shared__ float h0s[8 * FOUT];
    __shared__ float h1s[8 * FOUT];

    {
        const float4* gx = (const float4*)(nodes + (size_t)row0 * FIN);
        ((float4*)xs)[f] = gx[f];
    }
    __syncthreads();

    const float4* x4  = (const float4*)xs;
    const float4* h04 = (const float4*)h0s;
    const float4* h14 = (const float4*)h1s;

    // layer 0 (K=64) + CELU
    {
        const float4* wr = (const float4*)(W0 + (size_t)f * FIN);
        const float   bf = b0[f];
        float a[8];
        #pragma unroll
        for (int r = 0; r < 8; r++) a[r] = bf;
        #pragma unroll
        for (int k = 0; k < 16; k++) {
            float4 w = wr[k];
            #pragma unroll
            for (int r = 0; r < 8; r++) {
                float4 xv = x4[r * 16 + k];
                a[r] += w.x*xv.x + w.y*xv.y + w.z*xv.z + w.w*xv.w;
            }
        }
        #pragma unroll
        for (int r = 0; r < 8; r++) h0s[r * FOUT + f] = celu1(a[r]);
    }
    __syncthreads();

    // layer 1 (K=128) + CELU
    {
        const float4* wr = (const float4*)(W1 + (size_t)f * FOUT);
        const float   bf = b1[f];
        float a[8];
        #pragma unroll
        for (int r = 0; r < 8; r++) a[r] = bf;
        #pragma unroll
        for (int k = 0; k < 32; k++) {
            float4 w = wr[k];
            #pragma unroll
            for (int r = 0; r < 8; r++) {
                float4 hv = h04[r * 32 + k];
                a[r] += w.x*hv.x + w.y*hv.y + w.z*hv.z + w.w*hv.w;
            }
        }
        #pragma unroll
        for (int r = 0; r < 8; r++) h1s[r * FOUT + f] = celu1(a[r]);
    }
    __syncthreads();

    // layer 2 (K=128) -> g_h
    {
        const float4* wr = (const float4*)(W2 + (size_t)f * FOUT);
        const float   bf = b2[f];
        float a[8];
        #pragma unroll
        for (int r = 0; r < 8; r++) a[r] = bf;
        #pragma unroll
        for (int k = 0; k < 32; k++) {
            float4 w = wr[k];
            #pragma unroll
            for (int r = 0; r < 8; r++) {
                float4 hv = h14[r * 32 + k];
                a[r] += w.x*hv.x + w.y*hv.y + w.z*hv.z + w.w*hv.w;
            }
        }
        #pragma unroll
        for (int r = 0; r < 8; r++)
            g_h[(size_t)(row0 + r) * FOUT + f] = a[r];
    }
}

// ---------------------------------------------------------------------------
// K2: edges writer WITH fused i-partial reduction. (unchanged — proven)
// Tile: 64 (i) x 16 (j) per block. grid = (N/16, N/64, B) = 32x8x4, 256 thr.
// ---------------------------------------------------------------------------
__global__ __launch_bounds__(256) void k2_edges(
    const float* __restrict__ sk, float* __restrict__ edges)
{
    const int b  = blockIdx.z;
    const int iy = blockIdx.y;           // i-chunk 0..7
    const int i0 = iy * 64;
    const int j0 = blockIdx.x * 16;
    const int tid = threadIdx.x;

    __shared__ float4 spi [64][32];      // 32KB
    __shared__ float4 spjb[16][32];      // 8KB
    __shared__ float  ssk [64][16];      // 4KB

    const float4* gpi  = (const float4*)(g_pi  + ((size_t)(b * N_ + i0)) * FOUT);
    const float4* gpjb = (const float4*)(g_pjb + ((size_t)(b * N_ + j0)) * FOUT);
    #pragma unroll
    for (int t = tid; t < 2048; t += 256)
        spi[t >> 5][t & 31] = gpi[t];
    #pragma unroll
    for (int t = tid; t < 512; t += 256)
        spjb[t >> 5][t & 31] = gpjb[t];
    #pragma unroll
    for (int t = tid; t < 1024; t += 256) {
        int ii = t >> 4, jj = t & 15;
        ssk[ii][jj] = sk[((size_t)(b * N_ + i0 + ii)) * N_ + j0 + jj];
    }
    __syncthreads();

    const int lane = tid & 31;
    const int w    = tid >> 5;           // warp 0..7 -> jj in {w, w+8}

    const float4 c0 = spjb[w][lane];
    const float4 c1 = spjb[w + 8][lane];

    float4 acc0 = make_float4(0.f, 0.f, 0.f, 0.f);
    float4 acc1 = make_float4(0.f, 0.f, 0.f, 0.f);

    float4* __restrict__ e4 = (float4*)edges;
    const size_t base = ((size_t)(b * N_ + i0) * N_ + j0) * 32 + lane;

    #pragma unroll 4
    for (int ii = 0; ii < 64; ii++) {
        float4 a  = spi[ii][lane];
        float  s0 = ssk[ii][w];
        float  s1 = ssk[ii][w + 8];
        float4 e0, e1;
        e0.x = (a.x + c0.x) * s0;  e0.y = (a.y + c0.y) * s0;
        e0.z = (a.z + c0.z) * s0;  e0.w = (a.w + c0.w) * s0;
        e1.x = (a.x + c1.x) * s1;  e1.y = (a.y + c1.y) * s1;
        e1.z = (a.z + c1.z) * s1;  e1.w = (a.w + c1.w) * s1;
        size_t rbase = base + (size_t)ii * (N_ * 32);
        __stcs(&e4[rbase + (size_t)w * 32],        e0);
        __stcs(&e4[rbase + (size_t)(w + 8) * 32],  e1);
        acc0.x += e0.x; acc0.y += e0.y; acc0.z += e0.z; acc0.w += e0.w;
        acc1.x += e1.x; acc1.y += e1.y; acc1.z += e1.z; acc1.w += e1.w;
    }

    // write partials: g_part[b][iy][j][f]  (FULL edge sums — nothing added later)
    float4* p4 = (float4*)g_part;
    size_t pbase = (((size_t)(b * NCH + iy) * N_) + j0) * 32 + lane;
    p4[pbase + (size_t)w * 32]       = acc0;
    p4[pbase + (size_t)(w + 8) * 32] = acc1;
}

// ---------------------------------------------------------------------------
// K3: k1a-style — 8 j-rows/block, grid (N/8,B)=256 blocks, 128 threads.
//   Fold: 256 float4 slots (8 rows x 32); thread handles 2 slots x 8 chunks
//         = 16 independent LDG.128 -> nn SMEM.
//   GEMV: thread f streams its nW row (32 LDG.128, read only x256 blocks)
//         against 8 SMEM rows — 8 accumulator chains (k1a's proven shape).
// ---------------------------------------------------------------------------
__global__ __launch_bounds__(128) void k3_final(
    const float* __restrict__ nW, const float* __restrict__ nb,
    float* __restrict__ out1)
{
    const int b  = blockIdx.y;
    const int j0 = blockIdx.x * 8;
    const int f  = threadIdx.x;

    __shared__ float nn[8 * FOUT];       // 4KB
    float4* nn4 = (float4*)nn;

    // --- fold partials: 2 float4 slots per thread, 8 chunks each ---
    {
        const float4* p4 = (const float4*)g_part;
        #pragma unroll
        for (int sI = 0; sI < 2; sI++) {
            const int s  = f + sI * 128;     // 0..255
            const int jj = s >> 5;           // 0..7
            const int v  = s & 31;           // float4 slot in row
            const size_t rowslot = ((size_t)b * NCH * N_ + (j0 + jj)) * 32 + v;
            float4 a = make_float4(0.f, 0.f, 0.f, 0.f);
            #pragma unroll
            for (int c = 0; c < NCH; c++) {
                float4 p = p4[rowslot + (size_t)c * (N_ * 32)];
                a.x += p.x; a.y += p.y; a.z += p.z; a.w += p.w;
            }
            nn4[jj * 32 + v] = a;
        }
    }
    __syncthreads();

    // --- node_W GEMV for 8 rows (k1a loop shape) ---
    const float nbf = nb[f];
    float o[8];
    #pragma unroll
    for (int r = 0; r < 8; r++) o[r] = nbf;
    const float4* nwr = (const float4*)(nW + (size_t)f * FOUT);
    #pragma unroll
    for (int k = 0; k < 32; k++) {
        float4 w = nwr[k];
        #pragma unroll
        for (int r = 0; r < 8; r++) {
            float4 n = nn4[r * 32 + k];
            o[r] += w.x*n.x + w.y*n.y + w.z*n.z + w.w*n.w;
        }
    }

    const float* hr = g_h + ((size_t)(b * N_ + j0)) * FOUT;
    #pragma unroll
    for (int r = 0; r < 8; r++)
        out1[((size_t)(b * N_ + j0 + r)) * FOUT + f] = o[r] + hr[r * FOUT + f];
}

// ---------------------------------------------------------------------------
extern "C" void kernel_launch(void* const* d_in, const int* in_sizes, int n_in,
                              void* d_out, int out_size)
{
    const float* nodes = (const float*)d_in[0];
    const float* sk    = (const float*)d_in[1];
    const float* eW    = (const float*)d_in[2];
    const float* eb    = (const float*)d_in[3];
    const float* nW    = (const float*)d_in[4];
    const float* nb    = (const float*)d_in[5];
    const float* W0    = (const float*)d_in[6];
    const float* b0    = (const float*)d_in[7];
    const float* W1    = (const float*)d_in[8];
    const float* b1    = (const float*)d_in[9];
    const float* W2    = (const float*)d_in[10];
    const float* b2    = (const float*)d_in[11];

    float* out1  = (float*)d_out;                            // [B,N,F_OUT]
    float* edges = (float*)d_out + (size_t)B_ * N_ * FOUT;   // [B,N,N,F_OUT]

    // Side stream + events, created once (lazily, outside graph capture).
    static cudaStream_t s2 = nullptr;
    static cudaEvent_t  evFork = nullptr, evJoin = nullptr;
    if (s2 == nullptr) {
        cudaStreamCreateWithFlags(&s2, cudaStreamNonBlocking);
        cudaEventCreateWithFlags(&evFork, cudaEventDisableTiming);
        cudaEventCreateWithFlags(&evJoin, cudaEventDisableTiming);
    }

    // Fork: MLP runs concurrently with projections + edges writer.
    cudaEventRecord(evFork, 0);
    cudaStreamWaitEvent(s2, evFork, 0);
    k1b_mlp<<<(B_ * N_) / 8, 128, 0, s2>>>(nodes, W0, b0, W1, b1, W2, b2);
    cudaEventRecord(evJoin, s2);

    // Main stream: projections -> edges (+fused partial reduction)
    k1a_ew<<<(B_ * N_) / 8, 128>>>(nodes, eW, eb);

    dim3 g2(N_ / 16, N_ / 64, B_);
    k2_edges<<<g2, 256>>>(sk, edges);

    // Join: K3 needs both g_part (main stream) and g_h (side stream).
    cudaStreamWaitEvent(0, evJoin, 0);
    dim3 g3(N_ / 8, B_);
    k3_final<<<g3, 128>>>(nW, nb, out1);
}